// round 13
// baseline (speedup 1.0000x reference)
#include <cuda_runtime.h>
#include <cuda_bf16.h>

// QuantumCircuit via exact light-cone reduction.
// R13: phase 2 eliminated algebraically. Since v is real,
//   out[b] = v^T M v = sum_m z_m | sum_j W[m][j] v_j |^2,  z_m = +-1 (bit3 of m)
// so consumers compute u = W v directly from the circuit matrix W.
//
// grid = 8 CTAs x 512 threads:
//   producers (t < 256): phase0 gates -> phase1 W columns (shuffle butterfly),
//     write W transposed (WshT[m][j]) for row-major consumer reads.
//   consumers (t >= 256): 64 elements/CTA, 4 threads/element, each computes
//     4 of 16 u_m (re+im), squares, signs, 2x shfl_xor reduce.

__global__ void __launch_bounds__(512, 1)
qc_lightcone7_kernel(const float* __restrict__ inputs,   // [512,16]
                     const float* __restrict__ params,   // [4,16,3]
                     float* __restrict__ out) {          // [512]
    __shared__ float4 Ush[16][2];    // gate g: [0]=(U00.x,U00.y,U01.x,U01.y)
                                     //         [1]=(U10.x,U10.y,U11.x,U11.y)
    __shared__ float2 WshT[16][16];  // WshT[m][j] = <m|C|j>, rows 128B-aligned

    const int t = threadIdx.x;
    const unsigned FULL = 0xffffffffu;

    if (t < 256) {
        // =================== PRODUCER: warps 0-7 ===================
        if (t < 16) {
            const int layer = t >> 2;
            const int q     = t & 3;
            const float* gp = params + layer * 48 + q * 3;   // [4][16][3]
            const float phi = __ldg(gp + 0);
            const float th  = __ldg(gp + 1);
            const float om  = __ldg(gp + 2);
            float c, s, cp, sp, cm, sm;
            __sincosf(0.5f * th, &s, &c);
            __sincosf(0.5f * (phi + om), &sp, &cp);
            __sincosf(0.5f * (phi - om), &sm, &cm);
            // Rot = RZ(om) RY(th) RZ(phi)
            Ush[t][0] = make_float4( c * cp, -c * sp, -s * cm, -s * sm); // U00,U01
            Ush[t][1] = make_float4( s * cm, -s * sm,  c * cp,  c * sp); // U10,U11
        }
        asm volatile("bar.sync 1, 256;" ::: "memory");

        // ---- Phase 1: evolve column col; thread = (col = t>>4, m = t&15) ----
        {
            const int m   = t & 15;
            const int col = t >> 4;

            // Front-batch all 16 coefficient quads (selection thread-constant).
            float4 coef[16];
#pragma unroll
            for (int g = 0; g < 16; g++) {
                const int bit = 8 >> (g & 3);
                coef[g] = Ush[g][(m & bit) ? 1 : 0];
            }

            float2 st = make_float2((m == col) ? 1.0f : 0.0f, 0.0f);

#pragma unroll
            for (int layer = 0; layer < 4; layer++) {
#pragma unroll
                for (int q = 0; q < 4; q++) {
                    const int g   = layer * 4 + q;
                    const int bit = 8 >> q;
                    const float2 pr =
                        make_float2(__shfl_xor_sync(FULL, st.x, bit),
                                    __shfl_xor_sync(FULL, st.y, bit));
                    const bool hi = (m & bit) != 0;
                    const float2 a0 = hi ? pr : st;     // amp with bit=0
                    const float2 a1 = hi ? st : pr;     // amp with bit=1
                    const float4 u = coef[g];           // (cAx,cAy,cBx,cBy)
                    st.x = (u.x * a0.x - u.y * a0.y) + (u.z * a1.x - u.w * a1.y);
                    st.y = (u.x * a0.y + u.y * a0.x) + (u.z * a1.y + u.w * a1.x);
                }
                if (layer < 3) {
                    // CNOT chain as composed permutation: a'[m] = a[src(m)]
                    int i = m;
                    if (i & 2) i ^= 1;
                    if (i & 4) i ^= 2;
                    if (i & 8) i ^= 4;
                    const int srcLane = (t & 16) | i;
                    st.x = __shfl_sync(FULL, st.x, srcLane, 32);
                    st.y = __shfl_sync(FULL, st.y, srcLane, 32);
                }
            }
            // Fold last layer's permutation into write index x = src^{-1}(m).
            int i = m;
            if (i & 8) i ^= 4;
            if (i & 4) i ^= 2;
            if (i & 2) i ^= 1;
            WshT[i][col] = st;      // transposed store: W[m=i][j=col]
        }
        __syncthreads();   // hand W to consumer warps
    } else {
        // =================== CONSUMER: warps 8-15 ===================
        const int tt = t - 256;                 // 0..255
        const int e  = tt >> 2;                 // element within CTA (0..63)
        const int p  = tt & 3;                  // part: m in [4p, 4p+4)
        const int b  = blockIdx.x * 64 + e;

        // ---- Batch prep: overlapped with producer phases 0-1 ----
        float v[16];
        {
            const float4 x = *(const float4*)(inputs + b * 16);  // wires 0..3
            float c0, s0, c1, s1, c2, s2, c3, s3;
            __sincosf(0.5f * x.x, &s0, &c0);
            __sincosf(0.5f * x.y, &s1, &c1);
            __sincosf(0.5f * x.z, &s2, &c2);
            __sincosf(0.5f * x.w, &s3, &c3);
            float p01[4], p23[4];
            p01[0] = c0 * c1; p01[1] = c0 * s1;
            p01[2] = s0 * c1; p01[3] = s0 * s1;
            p23[0] = c2 * c3; p23[1] = c2 * s3;
            p23[2] = s2 * c3; p23[3] = s2 * s3;
#pragma unroll
            for (int j = 0; j < 16; j++)
                v[j] = p01[j >> 2] * p23[j & 3];
        }
        __syncthreads();   // wait for W

        // ---- u_m = sum_j W[m][j] v_j for this thread's 4 m's; acc z|u|^2 ----
        float acc = 0.0f;
#pragma unroll
        for (int i = 0; i < 4; i++) {
            const int m = p * 4 + i;
            const float4* Wm = (const float4*)&WshT[m][0];  // 8 quads = 16 cplx
            float re = 0.0f, im = 0.0f;
#pragma unroll
            for (int jq = 0; jq < 8; jq++) {
                const float4 w = Wm[jq];          // (W.x, W.y) x2
                const float vj0 = v[jq * 2 + 0];
                const float vj1 = v[jq * 2 + 1];
                re = fmaf(w.x, vj0, re);
                im = fmaf(w.y, vj0, im);
                re = fmaf(w.z, vj1, re);
                im = fmaf(w.w, vj1, im);
            }
            const float s2 = re * re + im * im;
            acc += (m & 8) ? -s2 : s2;            // z_m = (-1)^{bit3}
        }
        acc += __shfl_xor_sync(FULL, acc, 1);
        acc += __shfl_xor_sync(FULL, acc, 2);
        if (p == 0) out[b] = acc;
    }
}

extern "C" void kernel_launch(void* const* d_in, const int* in_sizes, int n_in,
                              void* d_out, int out_size) {
    const float* inputs = (const float*)d_in[0];   // [512,16]
    const float* params = (const float*)d_in[1];   // [4,16,3]
    float* out = (float*)d_out;                    // [512]
    qc_lightcone7_kernel<<<8, 512>>>(inputs, params, out);
}

// round 14
// speedup vs baseline: 1.3029x; 1.3029x over previous
#include <cuda_runtime.h>
#include <cuda_bf16.h>

// QuantumCircuit via exact light-cone reduction: out[b] = v_b^T M v_b,
// M = Re(C^dag Z0 C) restricted to wires {0..3}, v_b = real RY product state.
//
// R14 = R12 (warp-specialized winner) + Wsh row padding 16->18 float2:
// Phase-2 row reads at stride 128B were 16-way bank conflicted (all k's on the
// same 4 banks); 144B rows give bank=(4k+4mm)%32 -> 2-way. Phase-1 writes
// (col*36 + i*2 words) remain conflict-free.

__global__ void __launch_bounds__(512, 1)
qc_lightcone8_kernel(const float* __restrict__ inputs,   // [512,16]
                     const float* __restrict__ params,   // [4,16,3]
                     float* __restrict__ out) {          // [512]
    __shared__ float4 Ush[16][2];    // gate g: [0]=(U00.x,U00.y,U01.x,U01.y)
                                     //         [1]=(U10.x,U10.y,U11.x,U11.y)
    __shared__ float2 Wsh[16][18];   // Wsh[col][amp], rows padded to 144B
    __shared__ float  Msh[16][16];

    const int t = threadIdx.x;
    const unsigned FULL = 0xffffffffu;

    if (t < 256) {
        // =================== PRODUCER: warps 0-7 ===================
        // ---- Phase 0: gate matrices; params LDG issued first thing ----
        if (t < 16) {
            const int layer = t >> 2;
            const int q     = t & 3;
            const float* gp = params + layer * 48 + q * 3;   // [4][16][3]
            const float phi = __ldg(gp + 0);
            const float th  = __ldg(gp + 1);
            const float om  = __ldg(gp + 2);
            float c, s, cp, sp, cm, sm;
            __sincosf(0.5f * th, &s, &c);
            __sincosf(0.5f * (phi + om), &sp, &cp);
            __sincosf(0.5f * (phi - om), &sm, &cm);
            // Rot = RZ(om) RY(th) RZ(phi)
            Ush[t][0] = make_float4( c * cp, -c * sp, -s * cm, -s * sm); // U00,U01
            Ush[t][1] = make_float4( s * cm, -s * sm,  c * cp,  c * sp); // U10,U11
        }
        asm volatile("bar.sync 1, 256;" ::: "memory");

        // ---- Phase 1: evolve W columns; thread = (col = t>>4, m = t&15) ----
        {
            const int m   = t & 15;
            const int col = t >> 4;

            // Front-batch all 16 coefficient quads (selection thread-constant).
            float4 coef[16];
#pragma unroll
            for (int g = 0; g < 16; g++) {
                const int bit = 8 >> (g & 3);
                coef[g] = Ush[g][(m & bit) ? 1 : 0];
            }

            float2 st = make_float2((m == col) ? 1.0f : 0.0f, 0.0f);

#pragma unroll
            for (int layer = 0; layer < 4; layer++) {
#pragma unroll
                for (int q = 0; q < 4; q++) {
                    const int g   = layer * 4 + q;
                    const int bit = 8 >> q;
                    const float2 pr =
                        make_float2(__shfl_xor_sync(FULL, st.x, bit),
                                    __shfl_xor_sync(FULL, st.y, bit));
                    const bool hi = (m & bit) != 0;
                    const float2 a0 = hi ? pr : st;     // amp with bit=0
                    const float2 a1 = hi ? st : pr;     // amp with bit=1
                    const float4 u = coef[g];           // (cAx,cAy,cBx,cBy)
                    st.x = u.x * a0.x - u.y * a0.y + u.z * a1.x - u.w * a1.y;
                    st.y = u.x * a0.y + u.y * a0.x + u.z * a1.y + u.w * a1.x;
                }
                if (layer < 3) {
                    // CNOT chain as composed permutation: a'[m] = a[src(m)]
                    int i = m;
                    if (i & 2) i ^= 1;
                    if (i & 4) i ^= 2;
                    if (i & 8) i ^= 4;
                    const int srcLane = (t & 16) | i;
                    st.x = __shfl_sync(FULL, st.x, srcLane, 32);
                    st.y = __shfl_sync(FULL, st.y, srcLane, 32);
                }
            }
            // Fold last layer's permutation into the write index (inverse).
            int i = m;
            if (i & 8) i ^= 4;
            if (i & 4) i ^= 2;
            if (i & 2) i ^= 1;
            Wsh[col][i] = st;
        }
        asm volatile("bar.sync 1, 256;" ::: "memory");

        // ---- Phase 2: M[j][k] = sum_m z_m Re(conj(W[j][m]) W[k][m]) ----
        {
            const int j = t >> 4;
            const int k = t & 15;
            const float4* Wj = (const float4*)&Wsh[j][0];  // first 8 quads/row
            const float4* Wk = (const float4*)&Wsh[k][0];
            float accp = 0.0f, accm = 0.0f;                // m<8 : +, m>=8 : -
#pragma unroll
            for (int mm = 0; mm < 8; mm++) {
                const float4 a = Wj[mm];
                const float4 b = Wk[mm];
                const float d = a.x * b.x + a.y * b.y + a.z * b.z + a.w * b.w;
                if (mm < 4) accp += d; else accm += d;
            }
            Msh[j][k] = accp - accm;
        }
        __syncthreads();   // hand M to consumer warps (arrival-count sync)
    } else {
        // =================== CONSUMER: warps 8-15 ===================
        const int tt   = t - 256;               // 0..255
        const int b    = blockIdx.x * 128 + (tt >> 1);
        const int half = tt & 1;                // rows [8*half, 8*half+8)

        // ---- Batch prep: fully overlapped with producer phases 0-2 ----
        float v[16];
        {
            const float4 x = *(const float4*)(inputs + b * 16);  // wires 0..3
            float c0, s0, c1, s1, c2, s2, c3, s3;
            __sincosf(0.5f * x.x, &s0, &c0);
            __sincosf(0.5f * x.y, &s1, &c1);
            __sincosf(0.5f * x.z, &s2, &c2);
            __sincosf(0.5f * x.w, &s3, &c3);
            float p01[4], p23[4];
            p01[0] = c0 * c1; p01[1] = c0 * s1;
            p01[2] = s0 * c1; p01[3] = s0 * s1;
            p23[0] = c2 * c3; p23[1] = c2 * s3;
            p23[2] = s2 * c3; p23[3] = s2 * s3;
#pragma unroll
            for (int j = 0; j < 16; j++)
                v[j] = p01[j >> 2] * p23[j & 3];
        }
        __syncthreads();   // wait for M

        // ---- Phase 3: quadratic form, 2 threads per element ----
        const float4* M4 = (const float4*)Msh;
        float acc = 0.0f;
#pragma unroll
        for (int jj = 0; jj < 8; jj++) {
            const int j = half * 8 + jj;
            float row = 0.0f;
#pragma unroll
            for (int kk = 0; kk < 4; kk++) {
                const float4 mrow = M4[j * 4 + kk];
                row = fmaf(mrow.x, v[kk * 4 + 0], row);
                row = fmaf(mrow.y, v[kk * 4 + 1], row);
                row = fmaf(mrow.z, v[kk * 4 + 2], row);
                row = fmaf(mrow.w, v[kk * 4 + 3], row);
            }
            acc = fmaf(v[j], row, acc);
        }
        acc += __shfl_xor_sync(FULL, acc, 1);
        if (half == 0) out[b] = acc;
    }
}

extern "C" void kernel_launch(void* const* d_in, const int* in_sizes, int n_in,
                              void* d_out, int out_size) {
    const float* inputs = (const float*)d_in[0];   // [512,16]
    const float* params = (const float*)d_in[1];   // [4,16,3]
    float* out = (float*)d_out;                    // [512]
    qc_lightcone8_kernel<<<4, 512>>>(inputs, params, out);
}